// round 8
// baseline (speedup 1.0000x reference)
#include <cuda_runtime.h>
#include <cuda_bf16.h>
#include <cstdint>

// Problem constants
#define Bc 2
#define Hc 8
#define Nc 2048
#define Pc 64
#define Mc 4
#define Dc 256
#define NX 4096

// Tiling: CTA holds X tile (128 x 64) bf16; loops over NBLK d-blocks of 32 d's.
#define BN 128
#define BC 128
#define NBLK 4
#define TH 256
#define ROWB 144
#define OFF_A 0
#define OFF_B0 (BN * ROWB)
#define OFF_B1 (OFF_B0 + BC * ROWB)
#define SMEM_BYTES (OFF_B1 + BC * ROWB)   // 55,296 B -> 2 CTAs/SM

// Scratch: pre-gathered W (bf16x2) and pre-converted X (bf16x2).
// g_Wb[(bh*8 + jb)*128 + c][32]   rows c = d'*4 + m for d = jb*32 + d'
// g_Xb[(bh*4096 + n)][32]
__device__ uint32_t g_Wb[16 * 1024 * 32];     // 2 MB
__device__ uint32_t g_Xb[16 * 4096 * 32];     // 8 MB

__device__ __forceinline__ uint32_t s2u(const void* p) {
    uint32_t a;
    asm("{ .reg .u64 t; cvta.to.shared.u64 t, %1; cvt.u32.u64 %0, t; }" : "=r"(a) : "l"(p));
    return a;
}
__device__ __forceinline__ uint32_t pack_bf16x2(float lo, float hi) {
    uint32_t r;
    asm("cvt.rn.bf16x2.f32 %0, %1, %2;" : "=r"(r) : "f"(hi), "f"(lo));
    return r;
}
__device__ __forceinline__ void cp16(uint32_t dst, const void* src) {
    asm volatile("cp.async.cg.shared.global [%0], [%1], 16;" :: "r"(dst), "l"(src));
}

// ---- Prep: one warp per 64-float row. Blocks [0,2048): W gather; [2048,10240): X cvt ----
__global__ void __launch_bounds__(TH) prep_kernel(
    const float* __restrict__ Q, const float* __restrict__ Km,
    const int* __restrict__ sk)
{
    const int warp = threadIdx.x >> 5, lane = threadIdx.x & 31;
    const int bx = blockIdx.x;
    if (bx < 2048) {
        const int rw = bx * 8 + warp;                 // [0, 16384)
        const int bh = rw >> 10, rem = rw & 1023;
        const int jb = rem >> 7, c = rem & 127;
        const int m = c & 3, d = jb * 32 + (c >> 2);
        const int b = bh >> 3;
        const int s = sk[(b * Mc + m) * Dc + d];
        const float* src = (s < Nc)
            ? (Q  + (size_t)bh * Nc * Pc + (size_t)s * Pc)
            : (Km + (size_t)bh * Nc * Pc + (size_t)(s - Nc) * Pc);
        float2 x = *(const float2*)(src + lane * 2);
        g_Wb[(size_t)rw * 32 + lane] = pack_bf16x2(x.x, x.y);
    } else {
        const int rx = (bx - 2048) * 8 + warp;        // [0, 65536)
        const int bh = rx >> 12, n = rx & 4095;
        const float* src = (n < Nc)
            ? (Q  + (size_t)bh * Nc * Pc + (size_t)n * Pc)
            : (Km + (size_t)bh * Nc * Pc + (size_t)(n - Nc) * Pc);
        float2 x = *(const float2*)(src + lane * 2);
        g_Xb[(size_t)rx * 32 + lane] = pack_bf16x2(x.x, x.y);
    }
}

__global__ void __launch_bounds__(TH, 2) sketch_attn_main(
    const float* __restrict__ sgn, float* __restrict__ out)
{
    extern __shared__ char smem[];
    const uint32_t sb = s2u(smem);
    const int tid = threadIdx.x;

    const int bh = blockIdx.z;
    const int n0 = blockIdx.x * BN;
    const int dbase = blockIdx.y * (NBLK * 32);

    // ---- Async fills: A tile + first W block (16B chunks, 4 per thread each) ----
    {
        const uint32_t* asrc = g_Xb + ((size_t)(bh << 12) + n0) * 32;
        #pragma unroll
        for (int it = 0; it < 4; it++) {
            int i = it * TH + tid;
            int r = i >> 3, v = i & 7;
            cp16(sb + OFF_A + r * ROWB + v * 16, asrc + (size_t)r * 32 + v * 4);
        }
        const int jb0 = blockIdx.y * NBLK;
        const uint32_t* wsrc = g_Wb + (size_t)((bh << 3) + jb0) * 128 * 32;
        #pragma unroll
        for (int it = 0; it < 4; it++) {
            int i = it * TH + tid;
            int c = i >> 3, v = i & 7;
            cp16(sb + OFF_B0 + c * ROWB + v * 16, wsrc + (size_t)c * 32 + v * 4);
        }
        asm volatile("cp.async.commit_group;" ::: "memory");
        asm volatile("cp.async.wait_group 0;" ::: "memory");
    }
    __syncthreads();

    // ---- Warp tiling: 2 (n) x 4 (c) warps; warp tile 64 x 32 ----
    const int lane = tid & 31, warp = tid >> 5;
    const int wn = warp & 1, wc = warp >> 1;
    const int na = wn * 64, ca = wc * 32;
    const int g = lane >> 2, q = lane & 3;
    const int m0 = (q & 1) * 2;
    const int half = (q & 1) * 2;

    const uint32_t aAddr = sb + OFF_A
        + (uint32_t)(na + (lane & 15)) * ROWB + (uint32_t)(lane >> 4) * 16;
    const uint32_t bLane =
        (uint32_t)(ca + ((lane >> 4) << 3) + (lane & 7)) * ROWB
        + (uint32_t)((lane >> 3) & 1) * 16;

    #pragma unroll
    for (int j = 0; j < NBLK; j++) {
        // Prefetch next W block asynchronously into the idle buffer.
        if (j < NBLK - 1) {
            const int jb = blockIdx.y * NBLK + j + 1;
            const uint32_t* wsrc = g_Wb + (size_t)((bh << 3) + jb) * 128 * 32;
            const uint32_t off = (j & 1) ? OFF_B0 : OFF_B1;
            #pragma unroll
            for (int it = 0; it < 4; it++) {
                int i = it * TH + tid;
                int c = i >> 3, v = i & 7;
                cp16(sb + off + c * ROWB + v * 16, wsrc + (size_t)c * 32 + v * 4);
            }
            asm volatile("cp.async.commit_group;" ::: "memory");
        }

        const uint32_t bAddr = sb + ((j & 1) ? OFF_B1 : OFF_B0) + bLane;
        const int d0 = dbase + j * 32;

        float acc[4][4][4];
        #pragma unroll
        for (int i = 0; i < 4; i++)
            #pragma unroll
            for (int jj = 0; jj < 4; jj++)
                #pragma unroll
                for (int r = 0; r < 4; r++)
                    acc[i][jj][r] = 0.0f;

        // K-loop: 4 steps of k16; 4x4 m16n8k16 grid per warp.
        #pragma unroll
        for (int k = 0; k < 4; k++) {
            const uint32_t ko = (uint32_t)k * 32;
            uint32_t a[4][4];
            #pragma unroll
            for (int i = 0; i < 4; i++)
                asm volatile("ldmatrix.sync.aligned.m8n8.x4.shared.b16 {%0,%1,%2,%3}, [%4];"
                             : "=r"(a[i][0]), "=r"(a[i][1]), "=r"(a[i][2]), "=r"(a[i][3])
                             : "r"(aAddr + (uint32_t)i * 16 * ROWB + ko));
            uint32_t bb[4][2];
            #pragma unroll
            for (int p = 0; p < 2; p++)
                asm volatile("ldmatrix.sync.aligned.m8n8.x4.shared.b16 {%0,%1,%2,%3}, [%4];"
                             : "=r"(bb[2*p][0]), "=r"(bb[2*p][1]),
                               "=r"(bb[2*p+1][0]), "=r"(bb[2*p+1][1])
                             : "r"(bAddr + (uint32_t)p * 16 * ROWB + ko));
            #pragma unroll
            for (int i = 0; i < 4; i++)
                #pragma unroll
                for (int jj = 0; jj < 4; jj++)
                    asm volatile(
                        "mma.sync.aligned.m16n8k16.row.col.f32.bf16.bf16.f32 "
                        "{%0,%1,%2,%3}, {%4,%5,%6,%7}, {%8,%9}, {%0,%1,%2,%3};\n"
                        : "+f"(acc[i][jj][0]), "+f"(acc[i][jj][1]),
                          "+f"(acc[i][jj][2]), "+f"(acc[i][jj][3])
                        : "r"(a[i][0]), "r"(a[i][1]), "r"(a[i][2]), "r"(a[i][3]),
                          "r"(bb[jj][0]), "r"(bb[jj][1]));
        }

        // Hoisted per-block sign coefficients (one pair per jj).
        float sA[4], sB[4];
        #pragma unroll
        for (int jj = 0; jj < 4; jj++) {
            const int d = d0 + wc * 8 + jj * 2 + (q >> 1);
            sA[jj] = sgn[m0 * Dc + d];
            sB[jj] = sgn[(m0 + 1) * Dc + d];
        }

        // Epilogue: exp + signed m-reduce (xor 1), d-assembly (xor 2) -> float4 STG.
        #pragma unroll
        for (int i = 0; i < 4; i++) {
            float e0[4], e1[4];
            #pragma unroll
            for (int jj = 0; jj < 4; jj++) {
                float t0 = sA[jj] * __expf(acc[i][jj][0]) + sB[jj] * __expf(acc[i][jj][1]);
                float t1 = sA[jj] * __expf(acc[i][jj][2]) + sB[jj] * __expf(acc[i][jj][3]);
                t0 += __shfl_xor_sync(0xffffffffu, t0, 1);
                t1 += __shfl_xor_sync(0xffffffffu, t1, 1);
                e0[jj] = t0; e1[jj] = t1;
            }
            float f0[4], f1[4];
            #pragma unroll
            for (int jj = 0; jj < 4; jj++) {
                f0[jj] = __shfl_xor_sync(0xffffffffu, e0[jj], 2);
                f1[jj] = __shfl_xor_sync(0xffffffffu, e1[jj], 2);
            }
            const bool lo = (q < 2);
            float4 v;
            v.x = lo ? e0[half]     : f1[half];
            v.y = lo ? f0[half]     : e1[half];
            v.z = lo ? e0[half + 1] : f1[half + 1];
            v.w = lo ? f0[half + 1] : e1[half + 1];
            const int n = n0 + na + i * 16 + g + (lo ? 0 : 8);
            const int dcol = d0 + wc * 8 + (q & 1) * 4;
            *(float4*)(out + ((size_t)bh * NX + n) * Dc + dcol) = v;
        }

        if (j < NBLK - 1)
            asm volatile("cp.async.wait_group 0;" ::: "memory");
        __syncthreads();   // buffer handoff
    }
}

extern "C" void kernel_launch(void* const* d_in, const int* in_sizes, int n_in,
                              void* d_out, int out_size)
{
    const float* Q  = (const float*)d_in[0];
    const float* K  = (const float*)d_in[1];
    const int*   sk = (const int*)d_in[2];
    const float* sg = (const float*)d_in[3];
    float* out = (float*)d_out;

    prep_kernel<<<10240, TH>>>(Q, K, sk);

    cudaFuncSetAttribute(sketch_attn_main,
                         cudaFuncAttributeMaxDynamicSharedMemorySize, SMEM_BYTES);
    dim3 grid(NX / BN, Dc / (NBLK * 32), Bc * Hc);   // (32, 2, 16)
    sketch_attn_main<<<grid, TH, SMEM_BYTES>>>(sg, out);
}

// round 10
// speedup vs baseline: 1.0284x; 1.0284x over previous
#include <cuda_runtime.h>
#include <cuda_bf16.h>
#include <cstdint>

// Problem constants
#define Bc 2
#define Hc 8
#define Nc 2048
#define Pc 64
#define Mc 4
#define Dc 256
#define NX 4096

#define BN 128
#define TH 256
#define ROWB 144
#define OFF_A 0
#define OFF_B0 (BN * ROWB)
#define OFF_B1 (OFF_B0 + BN * ROWB)
#define SMEM_BYTES (OFF_B1 + BN * ROWB)   // 55,296 B -> 2 CTAs/SM

#define GRID 304        // 2 CTAs x 152 SMs (GB300)
#define NU 4096         // work units: u = bh*256 + n0idx*8 + jb

// Scratch: pre-gathered W and pre-converted X, both bf16x2.
// g_Wb[(bh*8 + jb)*128 + c][32]  rows c = d'*4 + m, d = jb*32 + d'
// g_Xb[(bh*4096 + n)][32]
__device__ uint32_t g_Wb[16 * 1024 * 32];     // 2 MB
__device__ uint32_t g_Xb[16 * 4096 * 32];     // 8 MB

__device__ __forceinline__ uint32_t s2u(const void* p) {
    uint32_t a;
    asm("{ .reg .u64 t; cvta.to.shared.u64 t, %1; cvt.u32.u64 %0, t; }" : "=r"(a) : "l"(p));
    return a;
}
__device__ __forceinline__ uint32_t pack_bf16x2(float lo, float hi) {
    uint32_t r;
    asm("cvt.rn.bf16x2.f32 %0, %1, %2;" : "=r"(r) : "f"(hi), "f"(lo));
    return r;
}
__device__ __forceinline__ void cp16(uint32_t dst, const void* src) {
    asm volatile("cp.async.cg.shared.global [%0], [%1], 16;" :: "r"(dst), "l"(src));
}

// ---- Prep: 16 B of bf16x2 output per thread (8 fp32 in -> uint4 out) ----
// Threads [0, 131072): W gather. Threads [131072, 655360): X convert.
__global__ void __launch_bounds__(TH) prep_kernel(
    const float* __restrict__ Q, const float* __restrict__ Km,
    const int* __restrict__ sk)
{
    const int t = blockIdx.x * TH + threadIdx.x;
    const float* src;
    uint32_t* dst;
    if (t < 131072) {
        const int rw = t >> 3, v = t & 7;
        const int bh = rw >> 10, rem = rw & 1023;
        const int jb = rem >> 7, c = rem & 127;
        const int m = c & 3, d = jb * 32 + (c >> 2);
        const int s = sk[((bh >> 3) * Mc + m) * Dc + d];
        src = (s < Nc)
            ? (Q  + (size_t)bh * Nc * Pc + (size_t)s * Pc + v * 8)
            : (Km + (size_t)bh * Nc * Pc + (size_t)(s - Nc) * Pc + v * 8);
        dst = g_Wb + (size_t)rw * 32 + v * 4;
    } else {
        const int tx = t - 131072;
        const int rx = tx >> 3, v = tx & 7;
        const int bh = rx >> 12, n = rx & 4095;
        src = (n < Nc)
            ? (Q  + (size_t)bh * Nc * Pc + (size_t)n * Pc + v * 8)
            : (Km + (size_t)bh * Nc * Pc + (size_t)(n - Nc) * Pc + v * 8);
        dst = g_Xb + (size_t)rx * 32 + v * 4;
    }
    float4 x0 = *(const float4*)src;
    float4 x1 = *(const float4*)(src + 4);
    *(uint4*)dst = make_uint4(pack_bf16x2(x0.x, x0.y), pack_bf16x2(x0.z, x0.w),
                              pack_bf16x2(x1.x, x1.y), pack_bf16x2(x1.z, x1.w));
}

__global__ void __launch_bounds__(TH, 2) sketch_attn_persist(
    const float* __restrict__ sgn, float* __restrict__ out)
{
    extern __shared__ char smem[];
    const uint32_t sb = s2u(smem);
    const int tid = threadIdx.x;
    const int w = blockIdx.x;

    const int u0 = (NU * w) / GRID;
    const int u1 = (NU * (w + 1)) / GRID;

    const int lane = tid & 31, warp = tid >> 5;
    const int wn = warp & 1, wc = warp >> 1;
    const int na = wn * 64, ca = wc * 32;
    const int g = lane >> 2, q = lane & 3;
    const int m0 = (q & 1) * 2;
    const int half = (q & 1) * 2;

    const uint32_t aAddr = sb + OFF_A
        + (uint32_t)(na + (lane & 15)) * ROWB + (uint32_t)(lane >> 4) * 16;
    const uint32_t bLane =
        (uint32_t)(ca + ((lane >> 4) << 3) + (lane & 7)) * ROWB
        + (uint32_t)((lane >> 3) & 1) * 16;

    // Tile fill: 1024 16B chunks, 4 per thread (round-8 proven addressing).
    auto fillA = [&](int bh, int n0) {
        const uint32_t* asrc = g_Xb + ((size_t)(bh << 12) + n0) * 32;
        #pragma unroll
        for (int it = 0; it < 4; it++) {
            int i = it * TH + tid;
            int r = i >> 3, v = i & 7;
            cp16(sb + OFF_A + r * ROWB + v * 16, asrc + (size_t)r * 32 + v * 4);
        }
    };
    auto fillW = [&](int u, uint32_t off) {
        const int bh = u >> 8, jb = u & 7;
        const uint32_t* wsrc = g_Wb + (size_t)((bh << 3) + jb) * 128 * 32;
        #pragma unroll
        for (int it = 0; it < 4; it++) {
            int i = it * TH + tid;
            int c = i >> 3, v = i & 7;
            cp16(sb + off + c * ROWB + v * 16, wsrc + (size_t)c * 32 + v * 4);
        }
    };

    int curGroup = -1;

    for (int u = u0; u < u1; u++) {
        const int t = u - u0;
        const int bh = u >> 8;
        const int n0 = ((u >> 3) & 31) * 128;
        const int d0 = (u & 7) * 32;
        const int grp = u >> 3;

        if (grp != curGroup) {
            fillA(bh, n0);
            if (u == u0) fillW(u, OFF_B0);
            asm volatile("cp.async.commit_group;" ::: "memory");
            asm volatile("cp.async.wait_group 0;" ::: "memory");
            __syncthreads();
            curGroup = grp;
        }

        // Prefetch next unit's W into the idle buffer.
        if (u + 1 < u1) {
            fillW(u + 1, (t & 1) ? OFF_B0 : OFF_B1);
            asm volatile("cp.async.commit_group;" ::: "memory");
        }

        const uint32_t bAddr = sb + ((t & 1) ? OFF_B1 : OFF_B0) + bLane;

        float acc[4][4][4];
        #pragma unroll
        for (int i = 0; i < 4; i++)
            #pragma unroll
            for (int jj = 0; jj < 4; jj++)
                #pragma unroll
                for (int r = 0; r < 4; r++)
                    acc[i][jj][r] = 0.0f;

        #pragma unroll
        for (int k = 0; k < 4; k++) {
            const uint32_t ko = (uint32_t)k * 32;
            uint32_t a[4][4];
            #pragma unroll
            for (int i = 0; i < 4; i++)
                asm volatile("ldmatrix.sync.aligned.m8n8.x4.shared.b16 {%0,%1,%2,%3}, [%4];"
                             : "=r"(a[i][0]), "=r"(a[i][1]), "=r"(a[i][2]), "=r"(a[i][3])
                             : "r"(aAddr + (uint32_t)i * 16 * ROWB + ko));
            uint32_t bb[4][2];
            #pragma unroll
            for (int p = 0; p < 2; p++)
                asm volatile("ldmatrix.sync.aligned.m8n8.x4.shared.b16 {%0,%1,%2,%3}, [%4];"
                             : "=r"(bb[2*p][0]), "=r"(bb[2*p][1]),
                               "=r"(bb[2*p+1][0]), "=r"(bb[2*p+1][1])
                             : "r"(bAddr + (uint32_t)p * 16 * ROWB + ko));
            #pragma unroll
            for (int i = 0; i < 4; i++)
                #pragma unroll
                for (int jj = 0; jj < 4; jj++)
                    asm volatile(
                        "mma.sync.aligned.m16n8k16.row.col.f32.bf16.bf16.f32 "
                        "{%0,%1,%2,%3}, {%4,%5,%6,%7}, {%8,%9}, {%0,%1,%2,%3};\n"
                        : "+f"(acc[i][jj][0]), "+f"(acc[i][jj][1]),
                          "+f"(acc[i][jj][2]), "+f"(acc[i][jj][3])
                        : "r"(a[i][0]), "r"(a[i][1]), "r"(a[i][2]), "r"(a[i][3]),
                          "r"(bb[jj][0]), "r"(bb[jj][1]));
        }

        float sA[4], sB[4];
        #pragma unroll
        for (int jj = 0; jj < 4; jj++) {
            const int d = d0 + wc * 8 + jj * 2 + (q >> 1);
            sA[jj] = sgn[m0 * Dc + d];
            sB[jj] = sgn[(m0 + 1) * Dc + d];
        }

        // Epilogue: exp + signed m-reduce (xor 1), d-assembly (xor 2) -> float4 STG.
        #pragma unroll
        for (int i = 0; i < 4; i++) {
            float e0[4], e1[4];
            #pragma unroll
            for (int jj = 0; jj < 4; jj++) {
                float t0 = sA[jj] * __expf(acc[i][jj][0]) + sB[jj] * __expf(acc[i][jj][1]);
                float t1 = sA[jj] * __expf(acc[i][jj][2]) + sB[jj] * __expf(acc[i][jj][3]);
                t0 += __shfl_xor_sync(0xffffffffu, t0, 1);
                t1 += __shfl_xor_sync(0xffffffffu, t1, 1);
                e0[jj] = t0; e1[jj] = t1;
            }
            float f0[4], f1[4];
            #pragma unroll
            for (int jj = 0; jj < 4; jj++) {
                f0[jj] = __shfl_xor_sync(0xffffffffu, e0[jj], 2);
                f1[jj] = __shfl_xor_sync(0xffffffffu, e1[jj], 2);
            }
            const bool lo = (q < 2);
            float4 v;
            v.x = lo ? e0[half]     : f1[half];
            v.y = lo ? f0[half]     : e1[half];
            v.z = lo ? e0[half + 1] : f1[half + 1];
            v.w = lo ? f0[half + 1] : e1[half + 1];
            const int n = n0 + na + i * 16 + g + (lo ? 0 : 8);
            const int dcol = d0 + wc * 8 + (q & 1) * 4;
            *(float4*)(out + ((size_t)bh * NX + n) * Dc + dcol) = v;
        }

        if (u + 1 < u1)
            asm volatile("cp.async.wait_group 0;" ::: "memory");
        __syncthreads();   // buffer + A-tile handoff
    }
}

extern "C" void kernel_launch(void* const* d_in, const int* in_sizes, int n_in,
                              void* d_out, int out_size)
{
    const float* Q  = (const float*)d_in[0];
    const float* K  = (const float*)d_in[1];
    const int*   sk = (const int*)d_in[2];
    const float* sg = (const float*)d_in[3];
    float* out = (float*)d_out;

    prep_kernel<<<2560, TH>>>(Q, K, sk);

    cudaFuncSetAttribute(sketch_attn_persist,
                         cudaFuncAttributeMaxDynamicSharedMemorySize, SMEM_BYTES);
    sketch_attn_persist<<<GRID, TH, SMEM_BYTES>>>(sg, out);
}

// round 11
// speedup vs baseline: 1.0603x; 1.0311x over previous
#include <cuda_runtime.h>
#include <cuda_bf16.h>
#include <cstdint>

// Problem constants
#define Bc 2
#define Hc 8
#define Nc 2048
#define Pc 64
#define Mc 4
#define Dc 256
#define NX 4096

#define BN 128
#define TH 256
#define ROWB 144
#define OFF_A 0
#define OFF_B0 (BN * ROWB)
#define OFF_B1 (OFF_B0 + BN * ROWB)
#define SMEM_BYTES (OFF_B1 + BN * ROWB)   // 55,296 B -> 2 CTAs/SM

#define GRID 304        // 2 CTAs x 152 SMs
#define NU 4096         // units: u = bh*256 + n0idx*8 + jb (jb innermost)

// Scratch: pre-gathered W and pre-converted X, both bf16x2.
__device__ uint32_t g_Wb[16 * 1024 * 32];     // 2 MB
__device__ uint32_t g_Xb[16 * 4096 * 32];     // 8 MB

__device__ __forceinline__ uint32_t s2u(const void* p) {
    uint32_t a;
    asm("{ .reg .u64 t; cvta.to.shared.u64 t, %1; cvt.u32.u64 %0, t; }" : "=r"(a) : "l"(p));
    return a;
}
__device__ __forceinline__ uint32_t pack_bf16x2(float lo, float hi) {
    uint32_t r;
    asm("cvt.rn.bf16x2.f32 %0, %1, %2;" : "=r"(r) : "f"(hi), "f"(lo));
    return r;
}
__device__ __forceinline__ void cp16(uint32_t dst, const void* src) {
    asm volatile("cp.async.cg.shared.global [%0], [%1], 16;" :: "r"(dst), "l"(src));
}

// ---- Prep: 16 B of bf16x2 output per thread ----
__global__ void __launch_bounds__(TH) prep_kernel(
    const float* __restrict__ Q, const float* __restrict__ Km,
    const int* __restrict__ sk)
{
    const int t = blockIdx.x * TH + threadIdx.x;
    const float* src;
    uint32_t* dst;
    if (t < 131072) {
        const int rw = t >> 3, v = t & 7;
        const int bh = rw >> 10, rem = rw & 1023;
        const int jb = rem >> 7, c = rem & 127;
        const int m = c & 3, d = jb * 32 + (c >> 2);
        const int s = sk[((bh >> 3) * Mc + m) * Dc + d];
        src = (s < Nc)
            ? (Q  + (size_t)bh * Nc * Pc + (size_t)s * Pc + v * 8)
            : (Km + (size_t)bh * Nc * Pc + (size_t)(s - Nc) * Pc + v * 8);
        dst = g_Wb + (size_t)rw * 32 + v * 4;
    } else {
        const int tx = t - 131072;
        const int rx = tx >> 3, v = tx & 7;
        const int bh = rx >> 12, n = rx & 4095;
        src = (n < Nc)
            ? (Q  + (size_t)bh * Nc * Pc + (size_t)n * Pc + v * 8)
            : (Km + (size_t)bh * Nc * Pc + (size_t)(n - Nc) * Pc + v * 8);
        dst = g_Xb + (size_t)rx * 32 + v * 4;
    }
    float4 x0 = *(const float4*)src;
    float4 x1 = *(const float4*)(src + 4);
    *(uint4*)dst = make_uint4(pack_bf16x2(x0.x, x0.y), pack_bf16x2(x0.z, x0.w),
                              pack_bf16x2(x1.x, x1.y), pack_bf16x2(x1.z, x1.w));
}

__global__ void __launch_bounds__(TH, 2) sketch_attn_pair(
    const float* __restrict__ sgn, float* __restrict__ out)
{
    extern __shared__ char smem[];
    const uint32_t sb = s2u(smem);
    const int tid = threadIdx.x;

    const int u0 = (NU * blockIdx.x) / GRID;
    const int u1 = (NU * (blockIdx.x + 1)) / GRID;

    const int lane = tid & 31, warp = tid >> 5;
    const int wn = warp & 1, wc = warp >> 1;
    const int na = wn * 64, ca = wc * 32;
    const int g = lane >> 2, q = lane & 3;
    const int m0 = (q & 1) * 2;
    const int half = (q & 1) * 2;
    const int barid = 1 + wc;          // named barrier per warp pair

    const uint32_t aAddr = sb + OFF_A
        + (uint32_t)(na + (lane & 15)) * ROWB + (uint32_t)(lane >> 4) * 16;
    const uint32_t bLane =
        (uint32_t)(ca + ((lane >> 4) << 3) + (lane & 7)) * ROWB
        + (uint32_t)((lane >> 3) & 1) * 16;

    // A fill: whole CTA, 1024 chunks (round-8 addressing).
    auto fillA = [&](int bh, int n0) {
        const uint32_t* asrc = g_Xb + ((size_t)(bh << 12) + n0) * 32;
        #pragma unroll
        for (int it = 0; it < 4; it++) {
            int i = it * TH + tid;
            int r = i >> 3, v = i & 7;
            cp16(sb + OFF_A + r * ROWB + v * 16, asrc + (size_t)r * 32 + v * 4);
        }
    };
    // W fill: THIS warp fills its pair's quarter-slice rows [wc*32+wn*16, +16).
    auto fillW = [&](int u, uint32_t off) {
        const int bh = u >> 8, jb = u & 7;
        const uint32_t* wsrc = g_Wb + (size_t)((bh << 3) + jb) * 128 * 32;
        const int rbase = ca + wn * 16;
        #pragma unroll
        for (int it = 0; it < 4; it++) {
            int idx = it * 32 + lane;           // 0..127
            int r = rbase + (idx >> 3), v = idx & 7;
            cp16(sb + off + r * ROWB + v * 16, wsrc + (size_t)r * 32 + v * 4);
        }
    };

    int curGroup = -1;

    for (int u = u0; u < u1; u++) {
        const int t = u - u0;
        const int bh = u >> 8;
        const int n0 = ((u >> 3) & 31) * 128;
        const int d0 = (u & 7) * 32;
        const int grp = u >> 3;

        if (grp != curGroup) {
            __syncthreads();                 // all warps done with old A
            fillA(bh, n0);
            if (u == u0) fillW(u, OFF_B0);
            asm volatile("cp.async.commit_group;" ::: "memory");
            asm volatile("cp.async.wait_group 0;" ::: "memory");
            __syncthreads();                 // A (+first W) visible to all
            curGroup = grp;
        } else {
            // Buffer cur was prefetched by this pair at unit t-1: wait own copies,
            // then pair-barrier so the partner's slice half is also in smem.
            asm volatile("cp.async.wait_group 0;" ::: "memory");
            asm volatile("bar.sync %0, 64;" :: "r"(barid) : "memory");
        }

        const uint32_t bAddr = sb + ((t & 1) ? OFF_B1 : OFF_B0) + bLane;

        float acc[4][4][4];
        #pragma unroll
        for (int i = 0; i < 4; i++)
            #pragma unroll
            for (int jj = 0; jj < 4; jj++)
                #pragma unroll
                for (int r = 0; r < 4; r++)
                    acc[i][jj][r] = 0.0f;

        #pragma unroll
        for (int k = 0; k < 4; k++) {
            const uint32_t ko = (uint32_t)k * 32;
            uint32_t a[4][4];
            #pragma unroll
            for (int i = 0; i < 4; i++)
                asm volatile("ldmatrix.sync.aligned.m8n8.x4.shared.b16 {%0,%1,%2,%3}, [%4];"
                             : "=r"(a[i][0]), "=r"(a[i][1]), "=r"(a[i][2]), "=r"(a[i][3])
                             : "r"(aAddr + (uint32_t)i * 16 * ROWB + ko));
            uint32_t bb[4][2];
            #pragma unroll
            for (int p = 0; p < 2; p++)
                asm volatile("ldmatrix.sync.aligned.m8n8.x4.shared.b16 {%0,%1,%2,%3}, [%4];"
                             : "=r"(bb[2*p][0]), "=r"(bb[2*p][1]),
                               "=r"(bb[2*p+1][0]), "=r"(bb[2*p+1][1])
                             : "r"(bAddr + (uint32_t)p * 16 * ROWB + ko));
            #pragma unroll
            for (int i = 0; i < 4; i++)
                #pragma unroll
                for (int jj = 0; jj < 4; jj++)
                    asm volatile(
                        "mma.sync.aligned.m16n8k16.row.col.f32.bf16.bf16.f32 "
                        "{%0,%1,%2,%3}, {%4,%5,%6,%7}, {%8,%9}, {%0,%1,%2,%3};\n"
                        : "+f"(acc[i][jj][0]), "+f"(acc[i][jj][1]),
                          "+f"(acc[i][jj][2]), "+f"(acc[i][jj][3])
                        : "r"(a[i][0]), "r"(a[i][1]), "r"(a[i][2]), "r"(a[i][3]),
                          "r"(bb[jj][0]), "r"(bb[jj][1]));
        }

        // Prefetch next unit's W slice into the idle buffer.
        // Safe: pair bar above proved partner finished unit t-1's reads of it;
        // own reads (LDSM of unit t-1) precede in program order.
        if (u + 1 < u1 && (u + 1) >> 3 == grp + ((u & 7) == 7 ? 1 : 0)) { /* always true */ }
        if (u + 1 < u1) {
            fillW(u + 1, (t & 1) ? OFF_B0 : OFF_B1);
            asm volatile("cp.async.commit_group;" ::: "memory");
        }

        float sA[4], sB[4];
        #pragma unroll
        for (int jj = 0; jj < 4; jj++) {
            const int d = d0 + wc * 8 + jj * 2 + (q >> 1);
            sA[jj] = sgn[m0 * Dc + d];
            sB[jj] = sgn[(m0 + 1) * Dc + d];
        }

        // Barrier-free epilogue: exp + signed m-reduce (xor 1), d-assembly (xor 2).
        #pragma unroll
        for (int i = 0; i < 4; i++) {
            float e0[4], e1[4];
            #pragma unroll
            for (int jj = 0; jj < 4; jj++) {
                float t0 = sA[jj] * __expf(acc[i][jj][0]) + sB[jj] * __expf(acc[i][jj][1]);
                float t1 = sA[jj] * __expf(acc[i][jj][2]) + sB[jj] * __expf(acc[i][jj][3]);
                t0 += __shfl_xor_sync(0xffffffffu, t0, 1);
                t1 += __shfl_xor_sync(0xffffffffu, t1, 1);
                e0[jj] = t0; e1[jj] = t1;
            }
            float f0[4], f1[4];
            #pragma unroll
            for (int jj = 0; jj < 4; jj++) {
                f0[jj] = __shfl_xor_sync(0xffffffffu, e0[jj], 2);
                f1[jj] = __shfl_xor_sync(0xffffffffu, e1[jj], 2);
            }
            const bool lo = (q < 2);
            float4 v;
            v.x = lo ? e0[half]     : f1[half];
            v.y = lo ? f0[half]     : e1[half];
            v.z = lo ? e0[half + 1] : f1[half + 1];
            v.w = lo ? f0[half + 1] : e1[half + 1];
            const int n = n0 + na + i * 16 + g + (lo ? 0 : 8);
            const int dcol = d0 + wc * 8 + (q & 1) * 4;
            *(float4*)(out + ((size_t)bh * NX + n) * Dc + dcol) = v;
        }
    }
}

extern "C" void kernel_launch(void* const* d_in, const int* in_sizes, int n_in,
                              void* d_out, int out_size)
{
    const float* Q  = (const float*)d_in[0];
    const float* K  = (const float*)d_in[1];
    const int*   sk = (const int*)d_in[2];
    const float* sg = (const float*)d_in[3];
    float* out = (float*)d_out;

    prep_kernel<<<2560, TH>>>(Q, K, sk);

    cudaFuncSetAttribute(sketch_attn_pair,
                         cudaFuncAttributeMaxDynamicSharedMemorySize, SMEM_BYTES);
    sketch_attn_pair<<<GRID, TH, SMEM_BYTES>>>(sg, out);
}

// round 12
// speedup vs baseline: 1.4482x; 1.3658x over previous
#include <cuda_runtime.h>
#include <cuda_bf16.h>
#include <cstdint>

// Problem constants
#define Bc 2
#define Hc 8
#define Nc 2048
#define Pc 64
#define Mc 4
#define Dc 256
#define NX 4096

#define BN 128
#define TH 256
#define ROWB 144
#define OFF_A 0
#define OFF_B0 (BN * ROWB)
#define OFF_B1 (OFF_B0 + BN * ROWB)
#define SMEM_BYTES (OFF_B1 + BN * ROWB)   // 55,296 B -> 2 CTAs/SM

#define GRID 304        // 2 CTAs x 152 SMs
#define NU 4096         // units: u = bh*256 + n0idx*8 + jb (jb innermost)

// Scratch: pre-gathered W and pre-converted X, both bf16x2.
__device__ uint32_t g_Wb[16 * 1024 * 32];     // 2 MB
__device__ uint32_t g_Xb[16 * 4096 * 32];     // 8 MB

__device__ __forceinline__ uint32_t s2u(const void* p) {
    uint32_t a;
    asm("{ .reg .u64 t; cvta.to.shared.u64 t, %1; cvt.u32.u64 %0, t; }" : "=r"(a) : "l"(p));
    return a;
}
__device__ __forceinline__ uint32_t pack_bf16x2(float lo, float hi) {
    uint32_t r;
    asm("cvt.rn.bf16x2.f32 %0, %1, %2;" : "=r"(r) : "f"(hi), "f"(lo));
    return r;
}
__device__ __forceinline__ void cp16(uint32_t dst, const void* src) {
    asm volatile("cp.async.cg.shared.global [%0], [%1], 16;" :: "r"(dst), "l"(src));
}

// ---- Prep: 16 B of bf16x2 output per thread ----
__global__ void __launch_bounds__(TH) prep_kernel(
    const float* __restrict__ Q, const float* __restrict__ Km,
    const int* __restrict__ sk)
{
    const int t = blockIdx.x * TH + threadIdx.x;
    const float* src;
    uint32_t* dst;
    if (t < 131072) {
        const int rw = t >> 3, v = t & 7;
        const int bh = rw >> 10, rem = rw & 1023;
        const int jb = rem >> 7, c = rem & 127;
        const int m = c & 3, d = jb * 32 + (c >> 2);
        const int s = sk[((bh >> 3) * Mc + m) * Dc + d];
        src = (s < Nc)
            ? (Q  + (size_t)bh * Nc * Pc + (size_t)s * Pc + v * 8)
            : (Km + (size_t)bh * Nc * Pc + (size_t)(s - Nc) * Pc + v * 8);
        dst = g_Wb + (size_t)rw * 32 + v * 4;
    } else {
        const int tx = t - 131072;
        const int rx = tx >> 3, v = tx & 7;
        const int bh = rx >> 12, n = rx & 4095;
        src = (n < Nc)
            ? (Q  + (size_t)bh * Nc * Pc + (size_t)n * Pc + v * 8)
            : (Km + (size_t)bh * Nc * Pc + (size_t)(n - Nc) * Pc + v * 8);
        dst = g_Xb + (size_t)rx * 32 + v * 4;
    }
    float4 x0 = *(const float4*)src;
    float4 x1 = *(const float4*)(src + 4);
    *(uint4*)dst = make_uint4(pack_bf16x2(x0.x, x0.y), pack_bf16x2(x0.z, x0.w),
                              pack_bf16x2(x1.x, x1.y), pack_bf16x2(x1.z, x1.w));
}

__global__ void __launch_bounds__(TH, 2) sketch_attn_ilv(
    const float* __restrict__ sgn, float* __restrict__ out)
{
    extern __shared__ char smem[];
    const uint32_t sb = s2u(smem);
    const int tid = threadIdx.x;

    const int u0 = (NU * blockIdx.x) / GRID;
    const int u1 = (NU * (blockIdx.x + 1)) / GRID;

    const int lane = tid & 31, warp = tid >> 5;
    const int wn = warp & 1, wc = warp >> 1;
    const int na = wn * 64, ca = wc * 32;
    const int g = lane >> 2, q = lane & 3;
    const int m0 = (q & 1) * 2;
    const bool hi = (q & 1);
    const bool lo = (q < 2);
    const int barid = 1 + wc;

    const uint32_t aAddr = sb + OFF_A
        + (uint32_t)(na + (lane & 15)) * ROWB + (uint32_t)(lane >> 4) * 16;
    const uint32_t bLane =
        (uint32_t)(ca + ((lane >> 4) << 3) + (lane & 7)) * ROWB
        + (uint32_t)((lane >> 3) & 1) * 16;

    auto fillA = [&](int bh, int n0) {
        const uint32_t* asrc = g_Xb + ((size_t)(bh << 12) + n0) * 32;
        #pragma unroll
        for (int it = 0; it < 4; it++) {
            int i = it * TH + tid;
            int r = i >> 3, v = i & 7;
            cp16(sb + OFF_A + r * ROWB + v * 16, asrc + (size_t)r * 32 + v * 4);
        }
    };
    // W fill: this warp fills rows [wc*32 + wn*16, +16) of the tile.
    auto fillW = [&](int u, uint32_t off) {
        const int bh = u >> 8, jb = u & 7;
        const uint32_t* wsrc = g_Wb + (size_t)((bh << 3) + jb) * 128 * 32;
        const int rbase = ca + wn * 16;
        #pragma unroll
        for (int it = 0; it < 4; it++) {
            int idx = it * 32 + lane;
            int r = rbase + (idx >> 3), v = idx & 7;
            cp16(sb + off + r * ROWB + v * 16, wsrc + (size_t)r * 32 + v * 4);
        }
    };

    int curGroup = -1;

    for (int u = u0; u < u1; u++) {
        const int t = u - u0;
        const int bh = u >> 8;
        const int n0 = ((u >> 3) & 31) * 128;
        const int d0 = (u & 7) * 32;
        const int grp = u >> 3;

        if (grp != curGroup) {
            __syncthreads();                 // all warps done with old A
            fillA(bh, n0);
            if (u == u0) fillW(u, OFF_B0);
            asm volatile("cp.async.commit_group;" ::: "memory");
            asm volatile("cp.async.wait_group 0;" ::: "memory");
            __syncthreads();
            curGroup = grp;
        } else {
            asm volatile("cp.async.wait_group 0;" ::: "memory");
            asm volatile("bar.sync %0, 64;" :: "r"(barid) : "memory");
        }

        // Prefetch next unit's W slice NOW: full unit of MMA+exp hides the LDG.
        // Safe: pair barrier above proved the partner finished unit t-1's reads
        // of the idle buffer; own reads preceded in program order.
        if (u + 1 < u1) {
            fillW(u + 1, (t & 1) ? OFF_B0 : OFF_B1);
            asm volatile("cp.async.commit_group;" ::: "memory");
        }

        const uint32_t bAddr = sb + ((t & 1) ? OFF_B1 : OFF_B0) + bLane;

        // Hoist B fragments for all 4 k-steps (8 LDSM, 32 regs).
        uint32_t bb[4][4][2];   // [k][jj][2]
        #pragma unroll
        for (int k = 0; k < 4; k++) {
            const uint32_t ko = (uint32_t)k * 32;
            #pragma unroll
            for (int p = 0; p < 2; p++)
                asm volatile("ldmatrix.sync.aligned.m8n8.x4.shared.b16 {%0,%1,%2,%3}, [%4];"
                             : "=r"(bb[k][2*p][0]), "=r"(bb[k][2*p][1]),
                               "=r"(bb[k][2*p+1][0]), "=r"(bb[k][2*p+1][1])
                             : "r"(bAddr + (uint32_t)p * 16 * ROWB + ko));
        }

        // Per-unit sign coefficients.
        float sA[4], sB[4];
        #pragma unroll
        for (int jj = 0; jj < 4; jj++) {
            const int d = d0 + wc * 8 + jj * 2 + (q >> 1);
            sA[jj] = sgn[m0 * Dc + d];
            sB[jj] = sgn[(m0 + 1) * Dc + d];
        }

        // ---- i-major: per 16-row block, MMA then immediately its epilogue.
        //      exp/shfl of block i overlaps MMA of block i+1 (no barriers). ----
        #pragma unroll
        for (int i = 0; i < 4; i++) {
            uint32_t a[4][4];
            #pragma unroll
            for (int k = 0; k < 4; k++)
                asm volatile("ldmatrix.sync.aligned.m8n8.x4.shared.b16 {%0,%1,%2,%3}, [%4];"
                             : "=r"(a[k][0]), "=r"(a[k][1]), "=r"(a[k][2]), "=r"(a[k][3])
                             : "r"(aAddr + (uint32_t)i * 16 * ROWB + (uint32_t)k * 32));

            float acc[4][4];
            #pragma unroll
            for (int jj = 0; jj < 4; jj++)
                #pragma unroll
                for (int r = 0; r < 4; r++)
                    acc[jj][r] = 0.0f;

            #pragma unroll
            for (int k = 0; k < 4; k++)
                #pragma unroll
                for (int jj = 0; jj < 4; jj++)
                    asm volatile(
                        "mma.sync.aligned.m16n8k16.row.col.f32.bf16.bf16.f32 "
                        "{%0,%1,%2,%3}, {%4,%5,%6,%7}, {%8,%9}, {%0,%1,%2,%3};\n"
                        : "+f"(acc[jj][0]), "+f"(acc[jj][1]),
                          "+f"(acc[jj][2]), "+f"(acc[jj][3])
                        : "r"(a[k][0]), "r"(a[k][1]), "r"(a[k][2]), "r"(a[k][3]),
                          "r"(bb[k][jj][0]), "r"(bb[k][jj][1]));

            // Epilogue(i): exp + signed m-reduce (xor 1), then select + xor 2.
            float e0[4], e1[4];
            #pragma unroll
            for (int jj = 0; jj < 4; jj++) {
                float t0 = sA[jj] * __expf(acc[jj][0]) + sB[jj] * __expf(acc[jj][1]);
                float t1 = sA[jj] * __expf(acc[jj][2]) + sB[jj] * __expf(acc[jj][3]);
                t0 += __shfl_xor_sync(0xffffffffu, t0, 1);
                t1 += __shfl_xor_sync(0xffffffffu, t1, 1);
                e0[jj] = t0; e1[jj] = t1;
            }
            // Only the half-pair this lane needs survives; xor(2) partner has
            // the same half index, so 4 shuffles replace 8.
            float ea = hi ? e0[2] : e0[0];
            float eb = hi ? e0[3] : e0[1];
            float ec = hi ? e1[2] : e1[0];
            float ed = hi ? e1[3] : e1[1];
            float fa = __shfl_xor_sync(0xffffffffu, ea, 2);
            float fb = __shfl_xor_sync(0xffffffffu, eb, 2);
            float fc = __shfl_xor_sync(0xffffffffu, ec, 2);
            float fd = __shfl_xor_sync(0xffffffffu, ed, 2);
            float4 v;
            v.x = lo ? ea : fc;
            v.y = lo ? fa : ec;
            v.z = lo ? eb : fd;
            v.w = lo ? fb : ed;
            const int n = n0 + na + i * 16 + g + (lo ? 0 : 8);
            const int dcol = d0 + wc * 8 + (q & 1) * 4;
            *(float4*)(out + ((size_t)bh * NX + n) * Dc + dcol) = v;
        }
    }
}

extern "C" void kernel_launch(void* const* d_in, const int* in_sizes, int n_in,
                              void* d_out, int out_size)
{
    const float* Q  = (const float*)d_in[0];
    const float* K  = (const float*)d_in[1];
    const int*   sk = (const int*)d_in[2];
    const float* sg = (const float*)d_in[3];
    float* out = (float*)d_out;

    prep_kernel<<<2560, TH>>>(Q, K, sk);

    cudaFuncSetAttribute(sketch_attn_ilv,
                         cudaFuncAttributeMaxDynamicSharedMemorySize, SMEM_BYTES);
    sketch_attn_ilv<<<GRID, TH, SMEM_BYTES>>>(sg, out);
}

// round 13
// speedup vs baseline: 1.6201x; 1.1187x over previous
#include <cuda_runtime.h>
#include <cuda_bf16.h>
#include <cstdint>

// Problem constants
#define Bc 2
#define Hc 8
#define Nc 2048
#define Pc 64
#define Mc 4
#define Dc 256
#define NX 4096

#define TH 256
#define ROWB 144
#define SMEM_BYTES (128 * ROWB)       // A tile only: 18,432 B

#define GRID 304
#define NU 4096                        // u = bh*256 + n0idx*8 + jb (jb innermost)

#define LOG2E 1.4426950408889634f

// g_Wf: W in MMA-fragment order. Per tile (bh*8+jb): 4096 words laid out as
// [k(4)][c(128)][q(4)][h(2)] ; word(k,c,q,h) = bf16x2 of W[c][k*16 + h*8 + 2q .. +1],
// pre-scaled by log2(e). Lane (g,q) of warp reads (b0,b1) for (jj,k) as ONE
// coalesced LDG.64 at k*1024 + ca*8 + jj*64 + lane*2.
__device__ uint32_t g_Wf[16 * 8 * 4096];      // 2 MB
__device__ uint32_t g_Xb[16 * 4096 * 32];     // 8 MB, bf16x2 row-major

__device__ __forceinline__ uint32_t s2u(const void* p) {
    uint32_t a;
    asm("{ .reg .u64 t; cvta.to.shared.u64 t, %1; cvt.u32.u64 %0, t; }" : "=r"(a) : "l"(p));
    return a;
}
__device__ __forceinline__ uint32_t pack_bf16x2(float lo, float hi) {
    uint32_t r;
    asm("cvt.rn.bf16x2.f32 %0, %1, %2;" : "=r"(r) : "f"(hi), "f"(lo));
    return r;
}
__device__ __forceinline__ float ex2f(float x) {
    float r;
    asm("ex2.approx.ftz.f32 %0, %1;" : "=f"(r) : "f"(x));
    return r;
}
__device__ __forceinline__ void cp16(uint32_t dst, const void* src) {
    asm volatile("cp.async.cg.shared.global [%0], [%1], 16;" :: "r"(dst), "l"(src));
}

// ---- Prep ----
// Threads [0, 65536): W -> fragment layout, one thread per (tile, c, k), x log2e.
// Threads [65536, 589824): X -> bf16x2 rows, 16 B out per thread.
__global__ void __launch_bounds__(TH) prep_kernel(
    const float* __restrict__ Q, const float* __restrict__ Km,
    const int* __restrict__ sk)
{
    const int t = blockIdx.x * TH + threadIdx.x;
    if (t < 65536) {
        const int tile = t >> 9;              // bh*8 + jb
        const int rem = t & 511;
        const int c = rem >> 2, k = rem & 3;
        const int bh = tile >> 3, jb = tile & 7;
        const int m = c & 3, d = jb * 32 + (c >> 2);
        const int s = sk[((bh >> 3) * Mc + m) * Dc + d];
        const float* src = (s < Nc)
            ? (Q  + (size_t)bh * Nc * Pc + (size_t)s * Pc)
            : (Km + (size_t)bh * Nc * Pc + (size_t)(s - Nc) * Pc);
        src += k * 16;
        float4 f0 = *(const float4*)(src);
        float4 f1 = *(const float4*)(src + 4);
        float4 f2 = *(const float4*)(src + 8);
        float4 f3 = *(const float4*)(src + 12);
        uint32_t* dst = g_Wf + (size_t)tile * 4096 + k * 1024 + c * 8;
        // word j' = q*2 + h ; h=0 -> cols k16+2q, h=1 -> cols k16+8+2q
        *(uint4*)dst = make_uint4(
            pack_bf16x2(f0.x * LOG2E, f0.y * LOG2E),   // q0 h0
            pack_bf16x2(f2.x * LOG2E, f2.y * LOG2E),   // q0 h1
            pack_bf16x2(f0.z * LOG2E, f0.w * LOG2E),   // q1 h0
            pack_bf16x2(f2.z * LOG2E, f2.w * LOG2E));  // q1 h1
        *(uint4*)(dst + 4) = make_uint4(
            pack_bf16x2(f1.x * LOG2E, f1.y * LOG2E),   // q2 h0
            pack_bf16x2(f3.x * LOG2E, f3.y * LOG2E),   // q2 h1
            pack_bf16x2(f1.z * LOG2E, f1.w * LOG2E),   // q3 h0
            pack_bf16x2(f3.z * LOG2E, f3.w * LOG2E));  // q3 h1
    } else {
        const int tx = t - 65536;
        const int rx = tx >> 3, v = tx & 7;
        const int bh = rx >> 12, n = rx & 4095;
        const float* src = (n < Nc)
            ? (Q  + (size_t)bh * Nc * Pc + (size_t)n * Pc + v * 8)
            : (Km + (size_t)bh * Nc * Pc + (size_t)(n - Nc) * Pc + v * 8);
        float4 x0 = *(const float4*)src;
        float4 x1 = *(const float4*)(src + 4);
        *(uint4*)(g_Xb + (size_t)rx * 32 + v * 4) =
            make_uint4(pack_bf16x2(x0.x, x0.y), pack_bf16x2(x0.z, x0.w),
                       pack_bf16x2(x1.x, x1.y), pack_bf16x2(x1.z, x1.w));
    }
}

__global__ void __launch_bounds__(TH, 2) sketch_attn_regB(
    const float* __restrict__ sgn, float* __restrict__ out)
{
    extern __shared__ char smem[];
    const uint32_t sb = s2u(smem);
    const int tid = threadIdx.x;

    const int u0 = (NU * blockIdx.x) / GRID;
    const int u1 = (NU * (blockIdx.x + 1)) / GRID;

    const int lane = tid & 31, warp = tid >> 5;
    const int wn = warp & 1, wc = warp >> 1;
    const int na = wn * 64, ca = wc * 32;
    const int g = lane >> 2, q = lane & 3;
    const int m0 = (q & 1) * 2;
    const bool hi = (q & 1);
    const bool lo = (q < 2);

    const uint32_t aAddr = sb
        + (uint32_t)(na + (lane & 15)) * ROWB + (uint32_t)(lane >> 4) * 16;

    auto fillA = [&](int bh, int n0) {
        const uint32_t* asrc = g_Xb + ((size_t)(bh << 12) + n0) * 32;
        #pragma unroll
        for (int it = 0; it < 4; it++) {
            int i = it * TH + tid;
            int r = i >> 3, v = i & 7;
            cp16(sb + r * ROWB + v * 16, asrc + (size_t)r * 32 + v * 4);
        }
    };

    int curGroup = -1;

    for (int u = u0; u < u1; u++) {
        const int bh = u >> 8;
        const int n0 = ((u >> 3) & 31) * 128;
        const int d0 = (u & 7) * 32;
        const int grp = u >> 3;

        if (grp != curGroup) {
            __syncthreads();
            fillA(bh, n0);
            asm volatile("cp.async.commit_group;" ::: "memory");
            asm volatile("cp.async.wait_group 0;" ::: "memory");
            __syncthreads();
            curGroup = grp;
        }

        // ---- B fragments: 16 coalesced LDG.64 straight from fragment-order W ----
        const uint32_t* wf = g_Wf + (size_t)((bh << 3) + (u & 7)) * 4096
                           + ca * 8 + lane * 2;
        uint2 bb[4][4];   // [k][jj]
        #pragma unroll
        for (int k = 0; k < 4; k++)
            #pragma unroll
            for (int jj = 0; jj < 4; jj++)
                bb[k][jj] = *(const uint2*)(wf + k * 1024 + jj * 64);

        float sA[4], sB[4];
        #pragma unroll
        for (int jj = 0; jj < 4; jj++) {
            const int d = d0 + wc * 8 + jj * 2 + (q >> 1);
            sA[jj] = sgn[m0 * Dc + d];
            sB[jj] = sgn[(m0 + 1) * Dc + d];
        }

        // ---- i-major: MMA(i) then epilogue(i); exp of i overlaps MMA of i+1 ----
        #pragma unroll
        for (int i = 0; i < 4; i++) {
            uint32_t a[4][4];
            #pragma unroll
            for (int k = 0; k < 4; k++)
                asm volatile("ldmatrix.sync.aligned.m8n8.x4.shared.b16 {%0,%1,%2,%3}, [%4];"
                             : "=r"(a[k][0]), "=r"(a[k][1]), "=r"(a[k][2]), "=r"(a[k][3])
                             : "r"(aAddr + (uint32_t)i * 16 * ROWB + (uint32_t)k * 32));

            float acc[4][4];
            #pragma unroll
            for (int jj = 0; jj < 4; jj++)
                #pragma unroll
                for (int r = 0; r < 4; r++)
                    acc[jj][r] = 0.0f;

            #pragma unroll
            for (int k = 0; k < 4; k++)
                #pragma unroll
                for (int jj = 0; jj < 4; jj++)
                    asm volatile(
                        "mma.sync.aligned.m16n8k16.row.col.f32.bf16.bf16.f32 "
                        "{%0,%1,%2,%3}, {%4,%5,%6,%7}, {%8,%9}, {%0,%1,%2,%3};\n"
                        : "+f"(acc[jj][0]), "+f"(acc[jj][1]),
                          "+f"(acc[jj][2]), "+f"(acc[jj][3])
                        : "r"(a[k][0]), "r"(a[k][1]), "r"(a[k][2]), "r"(a[k][3]),
                          "r"(bb[k][jj].x), "r"(bb[k][jj].y));

            // Epilogue(i): products are pre-scaled by log2e -> raw ex2.
            float e0[4], e1[4];
            #pragma unroll
            for (int jj = 0; jj < 4; jj++) {
                float t0 = sA[jj] * ex2f(acc[jj][0]) + sB[jj] * ex2f(acc[jj][1]);
                float t1 = sA[jj] * ex2f(acc[jj][2]) + sB[jj] * ex2f(acc[jj][3]);
                t0 += __shfl_xor_sync(0xffffffffu, t0, 1);
                t1 += __shfl_xor_sync(0xffffffffu, t1, 1);
                e0[jj] = t0; e1[jj] = t1;
            }
            float ea = hi ? e0[2] : e0[0];
            float eb = hi ? e0[3] : e0[1];
            float ec = hi ? e1[2] : e1[0];
            float ed = hi ? e1[3] : e1[1];
            float fa = __shfl_xor_sync(0xffffffffu, ea, 2);
            float fb = __shfl_xor_sync(0xffffffffu, eb, 2);
            float fc = __shfl_xor_sync(0xffffffffu, ec, 2);
            float fd = __shfl_xor_sync(0xffffffffu, ed, 2);
            float4 v;
            v.x = lo ? ea : fc;
            v.y = lo ? fa : ec;
            v.z = lo ? eb : fd;
            v.w = lo ? fb : ed;
            const int n = n0 + na + i * 16 + g + (lo ? 0 : 8);
            const int dcol = d0 + wc * 8 + (q & 1) * 4;
            *(float4*)(out + ((size_t)bh * NX + n) * Dc + dcol) = v;
        }
    }
}

extern "C" void kernel_launch(void* const* d_in, const int* in_sizes, int n_in,
                              void* d_out, int out_size)
{
    const float* Q  = (const float*)d_in[0];
    const float* K  = (const float*)d_in[1];
    const int*   sk = (const int*)d_in[2];
    const float* sg = (const float*)d_in[3];
    float* out = (float*)d_out;

    prep_kernel<<<2304, TH>>>(Q, K, sk);

    cudaFuncSetAttribute(sketch_attn_regB,
                         cudaFuncAttributeMaxDynamicSharedMemorySize, SMEM_BYTES);
    sketch_attn_regB<<<GRID, TH, SMEM_BYTES>>>(sg, out);
}

// round 14
// speedup vs baseline: 1.8710x; 1.1548x over previous
#include <cuda_runtime.h>
#include <cuda_bf16.h>
#include <cstdint>

// Problem constants
#define Bc 2
#define Hc 8
#define Nc 2048
#define Pc 64
#define Mc 4
#define Dc 256
#define NX 4096

#define TH 256
#define GRID 304
#define NU 4096                 // u = bh*256 + nb*8 + jb (jb innermost)
#define LOG2E 1.4426950408889634f

// g_Wf: W in B-fragment order (round-13 layout):
//   per tile (bh*8+jb): [k(4)][c(128)][q(4)][h(2)] bf16x2 words, pre-scaled log2e.
// g_Xf: X in A-fragment order:
//   per (bh, nb(32), wn(2)): [i(4)][k(4)][lane(32)][4 words]; word r of lane (g,q):
//   r0=(g, kc+2q), r1=(g+8, kc+2q), r2=(g, kc+8+2q), r3=(g+8, kc+8+2q), bf16x2.
// g_Sf: sign coefficients per (jb, wc, lane): [sA0..3, sB0..3] f32.
__device__ uint32_t g_Wf[16 * 8 * 4096];        // 2 MB
__device__ uint32_t g_Xf[16 * 32 * 2 * 2048];   // 8 MB
__device__ float    g_Sf[8 * 4 * 32 * 8];       // 32 KB

__device__ __forceinline__ uint32_t pack_bf16x2(float lo, float hi) {
    uint32_t r;
    asm("cvt.rn.bf16x2.f32 %0, %1, %2;" : "=r"(r) : "f"(hi), "f"(lo));
    return r;
}
__device__ __forceinline__ float ex2f(float x) {
    float r;
    asm("ex2.approx.ftz.f32 %0, %1;" : "=f"(r) : "f"(x));
    return r;
}

// ---- Prep ----
// t in [0, 65536): W fragments (x log2e).
// t in [65536, 66560): sign table.
// t in [66560, 590848): X A-fragments.
__global__ void __launch_bounds__(TH) prep_kernel(
    const float* __restrict__ Q, const float* __restrict__ Km,
    const int* __restrict__ sk, const float* __restrict__ sgn)
{
    const int t = blockIdx.x * TH + threadIdx.x;
    if (t < 65536) {
        const int tile = t >> 9;
        const int rem = t & 511;
        const int c = rem >> 2, k = rem & 3;
        const int bh = tile >> 3, jb = tile & 7;
        const int m = c & 3, d = jb * 32 + (c >> 2);
        const int s = sk[((bh >> 3) * Mc + m) * Dc + d];
        const float* src = (s < Nc)
            ? (Q  + (size_t)bh * Nc * Pc + (size_t)s * Pc)
            : (Km + (size_t)bh * Nc * Pc + (size_t)(s - Nc) * Pc);
        src += k * 16;
        float4 f0 = *(const float4*)(src);
        float4 f1 = *(const float4*)(src + 4);
        float4 f2 = *(const float4*)(src + 8);
        float4 f3 = *(const float4*)(src + 12);
        uint32_t* dst = g_Wf + (size_t)tile * 4096 + k * 1024 + c * 8;
        *(uint4*)dst = make_uint4(
            pack_bf16x2(f0.x * LOG2E, f0.y * LOG2E),
            pack_bf16x2(f2.x * LOG2E, f2.y * LOG2E),
            pack_bf16x2(f0.z * LOG2E, f0.w * LOG2E),
            pack_bf16x2(f2.z * LOG2E, f2.w * LOG2E));
        *(uint4*)(dst + 4) = make_uint4(
            pack_bf16x2(f1.x * LOG2E, f1.y * LOG2E),
            pack_bf16x2(f3.x * LOG2E, f3.y * LOG2E),
            pack_bf16x2(f1.z * LOG2E, f1.w * LOG2E),
            pack_bf16x2(f3.z * LOG2E, f3.w * LOG2E));
    } else if (t < 66560) {
        const int tx = t - 65536;               // (jb*4 + wc)*32 + lane
        const int lane = tx & 31, wc = (tx >> 5) & 3, jb = tx >> 7;
        const int q = lane & 3;
        const int m0 = (q & 1) * 2;
        float* dst = g_Sf + (size_t)tx * 8;
        #pragma unroll
        for (int jj = 0; jj < 4; jj++) {
            const int d = jb * 32 + wc * 8 + jj * 2 + (q >> 1);
            dst[jj]     = sgn[m0 * Dc + d];
            dst[jj + 4] = sgn[(m0 + 1) * Dc + d];
        }
    } else {
        const int tx = t - 66560;               // [bh][nb][wn][i][k][lane]
        const int lane = tx & 31;
        const int k = (tx >> 5) & 3;
        const int i = (tx >> 7) & 3;
        const int wn = (tx >> 9) & 1;
        const int nb = (tx >> 10) & 31;
        const int bh = tx >> 15;
        const int g = lane >> 2, q = lane & 3;
        const int row0 = nb * 128 + wn * 64 + i * 16 + g;
        const int kc = k * 16 + 2 * q;
        auto ldx = [&](int n, int col) -> uint32_t {
            const float* src = (n < Nc)
                ? (Q  + (size_t)bh * Nc * Pc + (size_t)n * Pc + col)
                : (Km + (size_t)bh * Nc * Pc + (size_t)(n - Nc) * Pc + col);
            float2 v = *(const float2*)src;
            return pack_bf16x2(v.x, v.y);
        };
        *(uint4*)(g_Xf + (size_t)tx * 4) = make_uint4(
            ldx(row0,     kc), ldx(row0 + 8, kc),
            ldx(row0,     kc + 8), ldx(row0 + 8, kc + 8));
    }
}

__global__ void __launch_bounds__(TH, 2) sketch_attn_reg(
    float* __restrict__ out)
{
    const int tid = threadIdx.x;
    const int u0 = (NU * blockIdx.x) / GRID;
    const int u1 = (NU * (blockIdx.x + 1)) / GRID;

    const int lane = tid & 31, warp = tid >> 5;
    const int wn = warp & 1, wc = warp >> 1;
    const int na = wn * 64, ca = wc * 32;
    const int g = lane >> 2, q = lane & 3;
    const bool hi = (q & 1);
    const bool lo = (q < 2);

    uint4 A[4][4];          // register-resident A fragments (64 regs)
    int curGroup = -1;

    for (int u = u0; u < u1; u++) {
        const int bh = u >> 8;
        const int nb = (u >> 3) & 31;
        const int jb = u & 7;
        const int grp = u >> 3;

        if (grp != curGroup) {
            const uint4* xf = (const uint4*)(g_Xf
                + ((size_t)((bh * 32 + nb) * 2 + wn)) * 2048) + lane;
            #pragma unroll
            for (int i = 0; i < 4; i++)
                #pragma unroll
                for (int k = 0; k < 4; k++)
                    A[i][k] = xf[(i * 4 + k) * 32];
            curGroup = grp;
        }

        // B fragments: 16 coalesced LDG.64 (L2-hot).
        const uint32_t* wf = g_Wf + (size_t)((bh << 3) + jb) * 4096
                           + ca * 8 + lane * 2;
        uint2 bb[4][4];
        #pragma unroll
        for (int k = 0; k < 4; k++)
            #pragma unroll
            for (int jj = 0; jj < 4; jj++)
                bb[k][jj] = *(const uint2*)(wf + k * 1024 + jj * 64);

        // Sign coefficients: 2 LDG.128.
        const float4* sf = (const float4*)(g_Sf
            + ((size_t)(jb * 4 + wc) * 32 + lane) * 8);
        float4 sAv = sf[0], sBv = sf[1];
        const float sA[4] = {sAv.x, sAv.y, sAv.z, sAv.w};
        const float sB[4] = {sBv.x, sBv.y, sBv.z, sBv.w};

        float* obase = out + (((size_t)bh * NX + nb * 128 + na + g + (lo ? 0 : 8)) * Dc)
                     + jb * 32 + wc * 8 + (q & 1) * 4;

        // i-major: MMA(i) then its epilogue; exp of i overlaps MMA of i+1.
        #pragma unroll
        for (int i = 0; i < 4; i++) {
            float acc[4][4];
            #pragma unroll
            for (int jj = 0; jj < 4; jj++)
                #pragma unroll
                for (int r = 0; r < 4; r++)
                    acc[jj][r] = 0.0f;

            #pragma unroll
            for (int k = 0; k < 4; k++)
                #pragma unroll
                for (int jj = 0; jj < 4; jj++)
                    asm volatile(
                        "mma.sync.aligned.m16n8k16.row.col.f32.bf16.bf16.f32 "
                        "{%0,%1,%2,%3}, {%4,%5,%6,%7}, {%8,%9}, {%0,%1,%2,%3};\n"
                        : "+f"(acc[jj][0]), "+f"(acc[jj][1]),
                          "+f"(acc[jj][2]), "+f"(acc[jj][3])
                        : "r"(A[i][k].x), "r"(A[i][k].y),
                          "r"(A[i][k].z), "r"(A[i][k].w),
                          "r"(bb[k][jj].x), "r"(bb[k][jj].y));

            float e0[4], e1[4];
            #pragma unroll
            for (int jj = 0; jj < 4; jj++) {
                float t0 = sA[jj] * ex2f(acc[jj][0]) + sB[jj] * ex2f(acc[jj][1]);
                float t1 = sA[jj] * ex2f(acc[jj][2]) + sB[jj] * ex2f(acc[jj][3]);
                t0 += __shfl_xor_sync(0xffffffffu, t0, 1);
                t1 += __shfl_xor_sync(0xffffffffu, t1, 1);
                e0[jj] = t0; e1[jj] = t1;
            }
            float ea = hi ? e0[2] : e0[0];
            float eb = hi ? e0[3] : e0[1];
            float ec = hi ? e1[2] : e1[0];
            float ed = hi ? e1[3] : e1[1];
            float fa = __shfl_xor_sync(0xffffffffu, ea, 2);
            float fb = __shfl_xor_sync(0xffffffffu, eb, 2);
            float fc = __shfl_xor_sync(0xffffffffu, ec, 2);
            float fd = __shfl_xor_sync(0xffffffffu, ed, 2);
            float4 v;
            v.x = lo ? ea : fc;
            v.y = lo ? fa : ec;
            v.z = lo ? eb : fd;
            v.w = lo ? fb : ed;
            *(float4*)(obase + (size_t)i * 16 * Dc) = v;
        }
    }
}

extern "C" void kernel_launch(void* const* d_in, const int* in_sizes, int n_in,
                              void* d_out, int out_size)
{
    const float* Q  = (const float*)d_in[0];
    const float* K  = (const float*)d_in[1];
    const int*   sk = (const int*)d_in[2];
    const float* sg = (const float*)d_in[3];
    float* out = (float*)d_out;

    prep_kernel<<<2308, TH>>>(Q, K, sk, sg);
    sketch_attn_reg<<<GRID, TH>>>(out);
}

// round 15
// speedup vs baseline: 2.0863x; 1.1151x over previous
#include <cuda_runtime.h>
#include <cuda_bf16.h>
#include <cstdint>

// Problem constants
#define Bc 2
#define Hc 8
#define Nc 2048
#define Pc 64
#define Mc 4
#define Dc 256
#define NX 4096

#define TH 256
#define GRID 304
#define NU 4096                 // u = bh*256 + nb*8 + jb (jb innermost)
#define LOG2E 1.4426950408889634f

// g_Wf: W fragments, per tile (bh*8+jb): [k(4)][c(128)][q(4)][h(2)] bf16x2,
//   pre-scaled by log2e. NEW c-mapping: c = wc*32 + m*8 + dlow,
//   d = jb*32 + wc*8 + dlow  ->  warp-tile jj == m (thread-local m-reduction).
// g_Xf: X A-fragments per (bh, nb, wn): [i(4)][k(4)][lane(32)][4 words].
// g_Sf: per (jb, wc, lane): [ s[m=0..3] for d=2q , s[m=0..3] for d=2q+1 ] f32.
__device__ uint32_t g_Wf[16 * 8 * 4096];        // 2 MB
__device__ uint32_t g_Xf[16 * 32 * 2 * 2048];   // 8 MB
__device__ float    g_Sf[8 * 4 * 32 * 8];       // 32 KB

__device__ __forceinline__ uint32_t pack_bf16x2(float lo, float hi) {
    uint32_t r;
    asm("cvt.rn.bf16x2.f32 %0, %1, %2;" : "=r"(r) : "f"(hi), "f"(lo));
    return r;
}
__device__ __forceinline__ float ex2f(float x) {
    float r;
    asm("ex2.approx.ftz.f32 %0, %1;" : "=f"(r) : "f"(x));
    return r;
}

// ---- Prep ----
// t in [0, 65536): W fragments.  [65536, 66560): sign table.  rest: X fragments.
__global__ void __launch_bounds__(TH) prep_kernel(
    const float* __restrict__ Q, const float* __restrict__ Km,
    const int* __restrict__ sk, const float* __restrict__ sgn)
{
    const int t = blockIdx.x * TH + threadIdx.x;
    if (t < 65536) {
        const int tile = t >> 9;
        const int rem = t & 511;
        const int c = rem >> 2, k = rem & 3;
        const int bh = tile >> 3, jb = tile & 7;
        // NEW mapping: jj == m
        const int m = (c >> 3) & 3;
        const int d = jb * 32 + (c >> 5) * 8 + (c & 7);
        const int s = sk[((bh >> 3) * Mc + m) * Dc + d];
        const float* src = (s < Nc)
            ? (Q  + (size_t)bh * Nc * Pc + (size_t)s * Pc)
            : (Km + (size_t)bh * Nc * Pc + (size_t)(s - Nc) * Pc);
        src += k * 16;
        float4 f0 = *(const float4*)(src);
        float4 f1 = *(const float4*)(src + 4);
        float4 f2 = *(const float4*)(src + 8);
        float4 f3 = *(const float4*)(src + 12);
        uint32_t* dst = g_Wf + (size_t)tile * 4096 + k * 1024 + c * 8;
        *(uint4*)dst = make_uint4(
            pack_bf16x2(f0.x * LOG2E, f0.y * LOG2E),
            pack_bf16x2(f2.x * LOG2E, f2.y * LOG2E),
            pack_bf16x2(f0.z * LOG2E, f0.w * LOG2E),
            pack_bf16x2(f2.z * LOG2E, f2.w * LOG2E));
        *(uint4*)(dst + 4) = make_uint4(
            pack_bf16x2(f1.x * LOG2E, f1.y * LOG2E),
            pack_bf16x2(f3.x * LOG2E, f3.y * LOG2E),
            pack_bf16x2(f1.z * LOG2E, f1.w * LOG2E),
            pack_bf16x2(f3.z * LOG2E, f3.w * LOG2E));
    } else if (t < 66560) {
        const int tx = t - 65536;               // (jb*4 + wc)*32 + lane
        const int lane = tx & 31, wc = (tx >> 5) & 3, jb = tx >> 7;
        const int q = lane & 3;
        const int dA = jb * 32 + wc * 8 + 2 * q;
        float* dst = g_Sf + (size_t)tx * 8;
        #pragma unroll
        for (int m = 0; m < 4; m++) {
            dst[m]     = sgn[m * Dc + dA];
            dst[m + 4] = sgn[m * Dc + dA + 1];
        }
    } else {
        const int tx = t - 66560;               // [bh][nb][wn][i][k][lane]
        const int lane = tx & 31;
        const int k = (tx >> 5) & 3;
        const int i = (tx >> 7) & 3;
        const int wn = (tx >> 9) & 1;
        const int nb = (tx >> 10) & 31;
        const int bh = tx >> 15;
        const int g = lane >> 2, q = lane & 3;
        const int row0 = nb * 128 + wn * 64 + i * 16 + g;
        const int kc = k * 16 + 2 * q;
        auto ldx = [&](int n, int col) -> uint32_t {
            const float* src = (n < Nc)
                ? (Q  + (size_t)bh * Nc * Pc + (size_t)n * Pc + col)
                : (Km + (size_t)bh * Nc * Pc + (size_t)(n - Nc) * Pc + col);
            float2 v = *(const float2*)src;
            return pack_bf16x2(v.x, v.y);
        };
        *(uint4*)(g_Xf + (size_t)tx * 4) = make_uint4(
            ldx(row0,     kc), ldx(row0 + 8, kc),
            ldx(row0,     kc + 8), ldx(row0 + 8, kc + 8));
    }
}

__global__ void __launch_bounds__(TH, 2) sketch_attn_noshfl(
    float* __restrict__ out)
{
    const int tid = threadIdx.x;
    const int u0 = (NU * blockIdx.x) / GRID;
    const int u1 = (NU * (blockIdx.x + 1)) / GRID;

    const int lane = tid & 31, warp = tid >> 5;
    const int wn = warp & 1, wc = warp >> 1;
    const int na = wn * 64, ca = wc * 32;
    const int g = lane >> 2, q = lane & 3;

    uint4 A[4][4];          // register-resident A fragments
    int curGroup = -1;

    for (int u = u0; u < u1; u++) {
        const int bh = u >> 8;
        const int nb = (u >> 3) & 31;
        const int jb = u & 7;
        const int grp = u >> 3;

        if (grp != curGroup) {
            const uint4* xf = (const uint4*)(g_Xf
                + ((size_t)((bh * 32 + nb) * 2 + wn)) * 2048) + lane;
            #pragma unroll
            for (int i = 0; i < 4; i++)
                #pragma unroll
                for (int k = 0; k < 4; k++)
                    A[i][k] = xf[(i * 4 + k) * 32];
            curGroup = grp;
        }

        // B fragments: 16 coalesced LDG.64 (L2-hot). jj == m.
        const uint32_t* wf = g_Wf + (size_t)((bh << 3) + jb) * 4096
                           + ca * 8 + lane * 2;
        uint2 bb[4][4];
        #pragma unroll
        for (int k = 0; k < 4; k++)
            #pragma unroll
            for (int m = 0; m < 4; m++)
                bb[k][m] = *(const uint2*)(wf + k * 1024 + m * 64);

        // Sign coefficients: s[m] for d=2q (sL) and d=2q+1 (sH).
        const float4* sf = (const float4*)(g_Sf
            + ((size_t)(jb * 4 + wc) * 32 + lane) * 8);
        float4 sLv = sf[0], sHv = sf[1];
        const float sL[4] = {sLv.x, sLv.y, sLv.z, sLv.w};
        const float sH[4] = {sHv.x, sHv.y, sHv.z, sHv.w};

        float* obase = out + (((size_t)bh * NX + nb * 128 + na + g) * Dc)
                     + jb * 32 + wc * 8 + 2 * q;

        // i-major: MMA(i) then thread-local epilogue (no shuffles at all).
        #pragma unroll
        for (int i = 0; i < 4; i++) {
            float acc[4][4];     // [m][r]; r: (g,dL),(g,dH),(g+8,dL),(g+8,dH)
            #pragma unroll
            for (int m = 0; m < 4; m++)
                #pragma unroll
                for (int r = 0; r < 4; r++)
                    acc[m][r] = 0.0f;

            #pragma unroll
            for (int k = 0; k < 4; k++)
                #pragma unroll
                for (int m = 0; m < 4; m++)
                    asm volatile(
                        "mma.sync.aligned.m16n8k16.row.col.f32.bf16.bf16.f32 "
                        "{%0,%1,%2,%3}, {%4,%5,%6,%7}, {%8,%9}, {%0,%1,%2,%3};\n"
                        : "+f"(acc[m][0]), "+f"(acc[m][1]),
                          "+f"(acc[m][2]), "+f"(acc[m][3])
                        : "r"(A[i][k].x), "r"(A[i][k].y),
                          "r"(A[i][k].z), "r"(A[i][k].w),
                          "r"(bb[k][m].x), "r"(bb[k][m].y));

            float v00 = 0.f, v01 = 0.f, v10 = 0.f, v11 = 0.f;
            #pragma unroll
            for (int m = 0; m < 4; m++) {
                v00 += sL[m] * ex2f(acc[m][0]);   // row g,   d = 2q
                v01 += sH[m] * ex2f(acc[m][1]);   // row g,   d = 2q+1
                v10 += sL[m] * ex2f(acc[m][2]);   // row g+8, d = 2q
                v11 += sH[m] * ex2f(acc[m][3]);   // row g+8, d = 2q+1
            }
            float* orow = obase + (size_t)i * 16 * Dc;
            *(float2*)orow               = make_float2(v00, v01);
            *(float2*)(orow + 8 * Dc)    = make_float2(v10, v11);
        }
    }
}

extern "C" void kernel_launch(void* const* d_in, const int* in_sizes, int n_in,
                              void* d_out, int out_size)
{
    const float* Q  = (const float*)d_in[0];
    const float* K  = (const float*)d_in[1];
    const int*   sk = (const int*)d_in[2];
    const float* sg = (const float*)d_in[3];
    float* out = (float*)d_out;

    prep_kernel<<<2308, TH>>>(Q, K, sk, sg);
    sketch_attn_noshfl<<<GRID, TH>>>(out);
}